// round 1
// baseline (speedup 1.0000x reference)
#include <cuda_runtime.h>
#include <cstdint>

// Problem constants (shapes fixed by the dataset)
#define MAX_N 100000
#define MAX_E 3200000
#define IN_DIM 256
#define HID 64
#define OUTD 10

// ---------------- scratch (device globals; no allocation allowed) ----------
__device__ int   g_is64;
__device__ int   g_rows[MAX_E];
__device__ int   g_cols[MAX_E];
__device__ float g_norm[MAX_E];
__device__ float g_dinv[MAX_N];          // deg accumulated here, then inverted in place
__device__ float g_h1[MAX_N * HID];      // GEMM outputs
__device__ float g_h2[MAX_N * HID];      // aggregation outputs / next-layer inputs
__device__ float g_h3[MAX_N * OUTD];

// ---------------- helpers --------------------------------------------------
__global__ void zero_kernel(float* p, long long n) {
    long long i = (long long)blockIdx.x * blockDim.x + threadIdx.x;
    long long stride = (long long)gridDim.x * blockDim.x;
    for (; i < n; i += stride) p[i] = 0.0f;
}

// Detect whether edge_index is int64 (all "high" 32-bit words zero) or int32.
__global__ void detect_kernel(const unsigned int* __restrict__ w, long long nwords) {
    __shared__ int nz;
    if (threadIdx.x == 0) nz = 0;
    __syncthreads();
    for (long long i = 1 + 2 * (long long)threadIdx.x; i < nwords && i < 4096;
         i += 2 * (long long)blockDim.x)
        if (w[i] != 0u) nz = 1;
    __syncthreads();
    if (threadIdx.x == 0) g_is64 = (nz == 0) ? 1 : 0;
}

__global__ void convert_edges(const void* __restrict__ ei, long long E) {
    long long e = (long long)blockIdx.x * blockDim.x + threadIdx.x;
    if (e >= E) return;
    if (g_is64) {
        const long long* p = (const long long*)ei;
        g_rows[e] = (int)p[e];
        g_cols[e] = (int)p[E + e];
    } else {
        const int* p = (const int*)ei;
        g_rows[e] = p[e];
        g_cols[e] = p[E + e];
    }
}

__global__ void deg_accum(const float* __restrict__ ew, long long E) {
    long long e = (long long)blockIdx.x * blockDim.x + threadIdx.x;
    if (e >= E) return;
    atomicAdd(&g_dinv[g_cols[e]], ew[e]);
}

__global__ void dinv_kernel(int n) {
    int i = blockIdx.x * blockDim.x + threadIdx.x;
    if (i >= n) return;
    float d = g_dinv[i];
    g_dinv[i] = (d > 0.0f) ? rsqrtf(fmaxf(d, 1e-12f)) : 0.0f;
}

__global__ void norm_kernel(const float* __restrict__ ew, long long E) {
    long long e = (long long)blockIdx.x * blockDim.x + threadIdx.x;
    if (e >= E) return;
    g_norm[e] = g_dinv[g_rows[e]] * ew[e] * g_dinv[g_cols[e]];
}

// ---------------- tiled SGEMM: C[M][64] = A[M][K] @ W[64][K]^T --------------
template <int K>
__global__ void gemm64(const float* __restrict__ A, const float* __restrict__ W,
                       float* __restrict__ C, int M) {
    __shared__ float As[16][64];
    __shared__ float Bs[16][64];
    int tid = threadIdx.x;            // 256 threads
    int tx = tid & 15, ty = tid >> 4; // 16 x 16
    int m0 = blockIdx.x * 64;
    float acc[4][4] = {};

    for (int k0 = 0; k0 < K; k0 += 16) {
        {   // load A tile 64x16 (transposed into As[k][m])
            int row = tid >> 2, kq = tid & 3;
            float4 v = make_float4(0.f, 0.f, 0.f, 0.f);
            if (m0 + row < M)
                v = *(const float4*)(A + (size_t)(m0 + row) * K + k0 + kq * 4);
            As[kq * 4 + 0][row] = v.x;
            As[kq * 4 + 1][row] = v.y;
            As[kq * 4 + 2][row] = v.z;
            As[kq * 4 + 3][row] = v.w;
        }
        {   // load W tile 64x16 (transposed into Bs[k][n])
            int n = tid >> 2, kq = tid & 3;
            float4 v = *(const float4*)(W + (size_t)n * K + k0 + kq * 4);
            Bs[kq * 4 + 0][n] = v.x;
            Bs[kq * 4 + 1][n] = v.y;
            Bs[kq * 4 + 2][n] = v.z;
            Bs[kq * 4 + 3][n] = v.w;
        }
        __syncthreads();
#pragma unroll
        for (int k = 0; k < 16; k++) {
            float4 a = *(const float4*)&As[k][ty * 4];
            float4 b = *(const float4*)&Bs[k][tx * 4];
            acc[0][0] += a.x * b.x; acc[0][1] += a.x * b.y; acc[0][2] += a.x * b.z; acc[0][3] += a.x * b.w;
            acc[1][0] += a.y * b.x; acc[1][1] += a.y * b.y; acc[1][2] += a.y * b.z; acc[1][3] += a.y * b.w;
            acc[2][0] += a.z * b.x; acc[2][1] += a.z * b.y; acc[2][2] += a.z * b.z; acc[2][3] += a.z * b.w;
            acc[3][0] += a.w * b.x; acc[3][1] += a.w * b.y; acc[3][2] += a.w * b.z; acc[3][3] += a.w * b.w;
        }
        __syncthreads();
    }
#pragma unroll
    for (int i = 0; i < 4; i++) {
        int row = m0 + ty * 4 + i;
        if (row < M) {
            float4 v = make_float4(acc[i][0], acc[i][1], acc[i][2], acc[i][3]);
            *(float4*)(C + (size_t)row * 64 + tx * 4) = v;
        }
    }
}

// C[M][10] = A[M][64] @ W[10][64]^T, one thread per row
__global__ void gemm_k64_n10(const float* __restrict__ A, const float* __restrict__ W,
                             float* __restrict__ C, int M) {
    __shared__ float Ws[OUTD * 64];
    for (int i = threadIdx.x; i < OUTD * 64; i += blockDim.x) Ws[i] = W[i];
    __syncthreads();
    int row = blockIdx.x * blockDim.x + threadIdx.x;
    if (row >= M) return;
    float acc[OUTD] = {};
    const float4* a4 = (const float4*)(A + (size_t)row * 64);
#pragma unroll
    for (int kq = 0; kq < 16; kq++) {
        float4 v = a4[kq];
#pragma unroll
        for (int o = 0; o < OUTD; o++) {
            acc[o] += v.x * Ws[o * 64 + kq * 4 + 0] + v.y * Ws[o * 64 + kq * 4 + 1] +
                      v.z * Ws[o * 64 + kq * 4 + 2] + v.w * Ws[o * 64 + kq * 4 + 3];
        }
    }
#pragma unroll
    for (int o = 0; o < OUTD; o++) C[(size_t)row * OUTD + o] = acc[o];
}

// ---------------- SpMM: out[col] += norm[e] * H[row], D=64 -----------------
__global__ void spmm64(const float* __restrict__ H, float* __restrict__ out, long long E) {
    long long idx = (long long)blockIdx.x * blockDim.x + threadIdx.x;
    long long total = E * 16;  // 16 float4 lanes per edge
    if (idx >= total) return;
    long long e = idx >> 4;
    int q = (int)(idx & 15);
    int r = g_rows[e], c = g_cols[e];
    float w = g_norm[e];
    float4 v = *(const float4*)(H + (size_t)r * 64 + q * 4);
    v.x *= w; v.y *= w; v.z *= w; v.w *= w;
    float* dst = out + (size_t)c * 64 + q * 4;
    asm volatile("red.global.add.v4.f32 [%0], {%1,%2,%3,%4};"
                 :: "l"(dst), "f"(v.x), "f"(v.y), "f"(v.z), "f"(v.w) : "memory");
}

// SpMM D=10, float2 lanes (5 per edge)
__global__ void spmm10(const float* __restrict__ H, float* __restrict__ out, long long E) {
    long long idx = (long long)blockIdx.x * blockDim.x + threadIdx.x;
    long long total = E * 5;
    if (idx >= total) return;
    long long e = idx / 5;
    int q = (int)(idx - e * 5);
    int r = g_rows[e], c = g_cols[e];
    float w = g_norm[e];
    float2 v = *(const float2*)(H + (size_t)r * OUTD + q * 2);
    v.x *= w; v.y *= w;
    float* dst = out + (size_t)c * OUTD + q * 2;
    asm volatile("red.global.add.v2.f32 [%0], {%1,%2};"
                 :: "l"(dst), "f"(v.x), "f"(v.y) : "memory");
}

// ---------------- epilogues ------------------------------------------------
__global__ void bias_relu64(float* __restrict__ h, const float* __restrict__ b, long long n) {
    long long i = (long long)blockIdx.x * blockDim.x + threadIdx.x;
    if (i >= n) return;
    float v = h[i] + b[i & 63];
    h[i] = v > 0.0f ? v : 0.0f;
}

__global__ void bias10(float* __restrict__ h, const float* __restrict__ b, long long n) {
    long long i = (long long)blockIdx.x * blockDim.x + threadIdx.x;
    if (i >= n) return;
    h[i] += b[(int)(i % OUTD)];
}

// ---------------- launch ---------------------------------------------------
static inline unsigned int cdiv(long long a, int b) { return (unsigned int)((a + b - 1) / b); }

extern "C" void kernel_launch(void* const* d_in, const int* in_sizes, int n_in,
                              void* d_out, int out_size) {
    const float* x  = (const float*)d_in[0];
    const void*  ei = d_in[1];
    const float* ew = (const float*)d_in[2];
    const float* W1 = (const float*)d_in[3];
    const float* b1 = (const float*)d_in[4];
    const float* W2 = (const float*)d_in[5];
    const float* b2 = (const float*)d_in[6];
    const float* W3 = (const float*)d_in[7];
    const float* b3 = (const float*)d_in[8];
    float* out = (float*)d_out;

    const int N = in_sizes[0] / IN_DIM;       // 100000
    const long long E = in_sizes[1] / 2;      // 3200000

    // device-global scratch addresses
    float *rows_f, *dinv_p, *h1, *h2, *h3;
    cudaGetSymbolAddress((void**)&dinv_p, g_dinv);
    cudaGetSymbolAddress((void**)&h1, g_h1);
    cudaGetSymbolAddress((void**)&h2, g_h2);
    cudaGetSymbolAddress((void**)&h3, g_h3);
    (void)rows_f; (void)n_in; (void)out_size;

    // --- preprocessing: edge dtype, int32 indices, degree, norm -------------
    detect_kernel<<<1, 256>>>((const unsigned int*)ei, E * 2);
    convert_edges<<<cdiv(E, 256), 256>>>(ei, E);
    zero_kernel<<<cdiv(N, 256), 256>>>(dinv_p, N);
    deg_accum<<<cdiv(E, 256), 256>>>(ew, E);
    dinv_kernel<<<cdiv(N, 256), 256>>>(N);
    norm_kernel<<<cdiv(E, 256), 256>>>(ew, E);

    // --- layer 1: h2 = relu(Anorm @ (x@W1^T) + b1) --------------------------
    gemm64<IN_DIM><<<cdiv(N, 64), 256>>>(x, W1, h1, N);
    zero_kernel<<<cdiv((long long)N * HID, 256), 256>>>(h2, (long long)N * HID);
    spmm64<<<cdiv(E * 16, 256), 256>>>(h1, h2, E);
    bias_relu64<<<cdiv((long long)N * HID, 256), 256>>>(h2, b1, (long long)N * HID);

    // --- layer 2 ------------------------------------------------------------
    gemm64<HID><<<cdiv(N, 64), 256>>>(h2, W2, h1, N);
    zero_kernel<<<cdiv((long long)N * HID, 256), 256>>>(h2, (long long)N * HID);
    spmm64<<<cdiv(E * 16, 256), 256>>>(h1, h2, E);
    bias_relu64<<<cdiv((long long)N * HID, 256), 256>>>(h2, b2, (long long)N * HID);

    // --- layer 3: out = Anorm @ (h2@W3^T) + b3 (no relu) --------------------
    gemm_k64_n10<<<cdiv(N, 128), 128>>>(h2, W3, h3, N);
    zero_kernel<<<cdiv((long long)N * OUTD, 256), 256>>>(out, (long long)N * OUTD);
    spmm10<<<cdiv(E * 5, 256), 256>>>(h3, out, E);
    bias10<<<cdiv((long long)N * OUTD, 256), 256>>>(out, b3, (long long)N * OUTD);
}

// round 2
// speedup vs baseline: 1.5092x; 1.5092x over previous
#include <cuda_runtime.h>
#include <cstdint>

// Problem constants (shapes fixed by the dataset)
#define MAX_N 100000
#define MAX_E 3200000
#define IN_DIM 256
#define HID 64
#define OUTD 10

// ---------------- scratch (device globals; no allocation allowed) ----------
__device__ int   g_is64;
__device__ int   g_rows[MAX_E];
__device__ int   g_cols[MAX_E];
__device__ float g_dinv[MAX_N];       // weighted in-degree, then d^{-1/2} in place
__device__ int   g_count[MAX_N];      // unweighted in-degree (CSR histogram)
__device__ int   g_start[MAX_N];      // CSR row (by col) offsets, exclusive
__device__ int   g_cursor[MAX_N];     // scatter cursors
__device__ int   g_bsums[256];        // scan block sums
__device__ int2  g_csre[MAX_E];       // CSR entries: {src_row, bitcast(norm)}
__device__ float g_h1[MAX_N * HID];   // GEMM outputs
__device__ float g_h2[MAX_N * HID];   // aggregation outputs / next-layer inputs
__device__ float g_h3[MAX_N * OUTD];

// ---------------- preprocessing --------------------------------------------
// Detect whether edge_index is int64 (all "high" 32-bit words zero) or int32.
__global__ void detect_kernel(const unsigned int* __restrict__ w, long long nwords) {
    __shared__ int nz;
    if (threadIdx.x == 0) nz = 0;
    __syncthreads();
    for (long long i = 1 + 2 * (long long)threadIdx.x; i < nwords && i < 4096;
         i += 2 * (long long)blockDim.x)
        if (w[i] != 0u) nz = 1;
    __syncthreads();
    if (threadIdx.x == 0) g_is64 = (nz == 0) ? 1 : 0;
}

__global__ void zero_nd(int n) {
    int i = blockIdx.x * blockDim.x + threadIdx.x;
    if (i >= n) return;
    g_dinv[i] = 0.0f;
    g_count[i] = 0;
}

// One pass: decode edges to int32, weighted degree (float) + histogram (int).
__global__ void convert_deg(const void* __restrict__ ei, const float* __restrict__ ew, int E) {
    int e = blockIdx.x * blockDim.x + threadIdx.x;
    if (e >= E) return;
    int r, c;
    if (g_is64) {
        const long long* p = (const long long*)ei;
        r = (int)p[e];
        c = (int)p[E + e];
    } else {
        const int* p = (const int*)ei;
        r = p[e];
        c = p[E + e];
    }
    g_rows[e] = r;
    g_cols[e] = c;
    atomicAdd(&g_dinv[c], ew[e]);
    atomicAdd(&g_count[c], 1);
}

__global__ void dinv_kernel(int n) {
    int i = blockIdx.x * blockDim.x + threadIdx.x;
    if (i >= n) return;
    float d = g_dinv[i];
    g_dinv[i] = (d > 0.0f) ? rsqrtf(fmaxf(d, 1e-12f)) : 0.0f;
}

// Per-block exclusive scan of g_count -> g_start (block-local) + block totals.
__global__ void scan_block(int n) {
    __shared__ int warp_sums[32];
    int i = blockIdx.x * 1024 + threadIdx.x;
    int v = (i < n) ? g_count[i] : 0;
    int lane = threadIdx.x & 31, wid = threadIdx.x >> 5;
    int x = v;
#pragma unroll
    for (int o = 1; o < 32; o <<= 1) {
        int y = __shfl_up_sync(~0u, x, o);
        if (lane >= o) x += y;
    }
    if (lane == 31) warp_sums[wid] = x;
    __syncthreads();
    if (wid == 0) {
        int s = warp_sums[lane];
#pragma unroll
        for (int o = 1; o < 32; o <<= 1) {
            int y = __shfl_up_sync(~0u, s, o);
            if (lane >= o) s += y;
        }
        warp_sums[lane] = s;
    }
    __syncthreads();
    int base = (wid > 0) ? warp_sums[wid - 1] : 0;
    int incl = x + base;
    if (i < n) g_start[i] = incl - v;
    if (threadIdx.x == 1023) g_bsums[blockIdx.x] = incl;
}

__global__ void scan_sums(int nb) {
    if (threadIdx.x != 0 || blockIdx.x != 0) return;
    int run = 0;
    for (int b = 0; b < nb; b++) {
        int t = g_bsums[b];
        g_bsums[b] = run;
        run += t;
    }
}

__global__ void add_offsets(int n) {
    int i = blockIdx.x * blockDim.x + threadIdx.x;
    if (i >= n) return;
    int s = g_start[i] + g_bsums[i >> 10];
    g_start[i] = s;
    g_cursor[i] = s;
}

// Compute per-edge norm and scatter edges into CSR (sorted by destination col).
__global__ void scatter_csr(const float* __restrict__ ew, int E) {
    int e = blockIdx.x * blockDim.x + threadIdx.x;
    if (e >= E) return;
    int r = g_rows[e], c = g_cols[e];
    float w = g_dinv[r] * ew[e] * g_dinv[c];
    int p = atomicAdd(&g_cursor[c], 1);
    g_csre[p] = make_int2(r, __float_as_int(w));
}

// ---------------- tiled SGEMM: C[M][64] = A[M][K] @ W[64][K]^T --------------
template <int K>
__global__ void gemm64(const float* __restrict__ A, const float* __restrict__ W,
                       float* __restrict__ C, int M) {
    __shared__ float As[16][64];
    __shared__ float Bs[16][64];
    int tid = threadIdx.x;            // 256 threads
    int tx = tid & 15, ty = tid >> 4; // 16 x 16
    int m0 = blockIdx.x * 64;
    float acc[4][4] = {};

    for (int k0 = 0; k0 < K; k0 += 16) {
        {   // load A tile 64x16 (transposed into As[k][m])
            int row = tid >> 2, kq = tid & 3;
            float4 v = make_float4(0.f, 0.f, 0.f, 0.f);
            if (m0 + row < M)
                v = *(const float4*)(A + (size_t)(m0 + row) * K + k0 + kq * 4);
            As[kq * 4 + 0][row] = v.x;
            As[kq * 4 + 1][row] = v.y;
            As[kq * 4 + 2][row] = v.z;
            As[kq * 4 + 3][row] = v.w;
        }
        {   // load W tile 64x16 (transposed into Bs[k][n])
            int n = tid >> 2, kq = tid & 3;
            float4 v = *(const float4*)(W + (size_t)n * K + k0 + kq * 4);
            Bs[kq * 4 + 0][n] = v.x;
            Bs[kq * 4 + 1][n] = v.y;
            Bs[kq * 4 + 2][n] = v.z;
            Bs[kq * 4 + 3][n] = v.w;
        }
        __syncthreads();
#pragma unroll
        for (int k = 0; k < 16; k++) {
            float4 a = *(const float4*)&As[k][ty * 4];
            float4 b = *(const float4*)&Bs[k][tx * 4];
            acc[0][0] += a.x * b.x; acc[0][1] += a.x * b.y; acc[0][2] += a.x * b.z; acc[0][3] += a.x * b.w;
            acc[1][0] += a.y * b.x; acc[1][1] += a.y * b.y; acc[1][2] += a.y * b.z; acc[1][3] += a.y * b.w;
            acc[2][0] += a.z * b.x; acc[2][1] += a.z * b.y; acc[2][2] += a.z * b.z; acc[2][3] += a.z * b.w;
            acc[3][0] += a.w * b.x; acc[3][1] += a.w * b.y; acc[3][2] += a.w * b.z; acc[3][3] += a.w * b.w;
        }
        __syncthreads();
    }
#pragma unroll
    for (int i = 0; i < 4; i++) {
        int row = m0 + ty * 4 + i;
        if (row < M) {
            float4 v = make_float4(acc[i][0], acc[i][1], acc[i][2], acc[i][3]);
            *(float4*)(C + (size_t)row * 64 + tx * 4) = v;
        }
    }
}

// C[M][10] = A[M][64] @ W[10][64]^T, one thread per row
__global__ void gemm_k64_n10(const float* __restrict__ A, const float* __restrict__ W,
                             float* __restrict__ C, int M) {
    __shared__ float Ws[OUTD * 64];
    for (int i = threadIdx.x; i < OUTD * 64; i += blockDim.x) Ws[i] = W[i];
    __syncthreads();
    int row = blockIdx.x * blockDim.x + threadIdx.x;
    if (row >= M) return;
    float acc[OUTD] = {};
    const float4* a4 = (const float4*)(A + (size_t)row * 64);
#pragma unroll
    for (int kq = 0; kq < 16; kq++) {
        float4 v = a4[kq];
#pragma unroll
        for (int o = 0; o < OUTD; o++) {
            acc[o] += v.x * Ws[o * 64 + kq * 4 + 0] + v.y * Ws[o * 64 + kq * 4 + 1] +
                      v.z * Ws[o * 64 + kq * 4 + 2] + v.w * Ws[o * 64 + kq * 4 + 3];
        }
    }
#pragma unroll
    for (int o = 0; o < OUTD; o++) C[(size_t)row * OUTD + o] = acc[o];
}

// ---------------- CSR gather SpMM, D=64, fused bias(+relu) -----------------
// One warp per destination node; each lane owns 2 feature dims (float2).
template <int RELU>
__global__ void spmm_gather64(const float* __restrict__ H, const float* __restrict__ b,
                              float* __restrict__ out, int N, int E) {
    int warp = (int)((blockIdx.x * (long long)blockDim.x + threadIdx.x) >> 5);
    int lane = threadIdx.x & 31;
    if (warp >= N) return;
    int s = g_start[warp];
    int e = (warp == N - 1) ? E : g_start[warp + 1];
    float2 acc = make_float2(0.0f, 0.0f);
    int j = s;
    // unroll by 2 for MLP on the index stream
    for (; j + 1 < e; j += 2) {
        int2 c0 = g_csre[j];
        int2 c1 = g_csre[j + 1];
        float w0 = __int_as_float(c0.y), w1 = __int_as_float(c1.y);
        float2 v0 = *(const float2*)(H + (size_t)c0.x * 64 + lane * 2);
        float2 v1 = *(const float2*)(H + (size_t)c1.x * 64 + lane * 2);
        acc.x += w0 * v0.x + w1 * v1.x;
        acc.y += w0 * v0.y + w1 * v1.y;
    }
    if (j < e) {
        int2 c0 = g_csre[j];
        float w0 = __int_as_float(c0.y);
        float2 v0 = *(const float2*)(H + (size_t)c0.x * 64 + lane * 2);
        acc.x += w0 * v0.x;
        acc.y += w0 * v0.y;
    }
    float2 bb = *(const float2*)(b + lane * 2);
    acc.x += bb.x; acc.y += bb.y;
    if (RELU) { acc.x = fmaxf(acc.x, 0.0f); acc.y = fmaxf(acc.y, 0.0f); }
    *(float2*)(out + (size_t)warp * 64 + lane * 2) = acc;
}

// CSR gather SpMM, D=10, fused bias. One warp per node; lanes 0..9 active for H.
__global__ void spmm_gather10(const float* __restrict__ H, const float* __restrict__ b,
                              float* __restrict__ out, int N, int E) {
    int warp = (int)((blockIdx.x * (long long)blockDim.x + threadIdx.x) >> 5);
    int lane = threadIdx.x & 31;
    if (warp >= N) return;
    int s = g_start[warp];
    int e = (warp == N - 1) ? E : g_start[warp + 1];
    float acc = 0.0f;
    for (int j = s; j < e; j++) {
        int2 c0 = g_csre[j];
        float w0 = __int_as_float(c0.y);
        float v = (lane < OUTD) ? H[(size_t)c0.x * OUTD + lane] : 0.0f;
        acc += w0 * v;
    }
    if (lane < OUTD) out[(size_t)warp * OUTD + lane] = acc + b[lane];
}

// ---------------- launch ---------------------------------------------------
static inline unsigned int cdiv(long long a, int b) { return (unsigned int)((a + b - 1) / b); }

extern "C" void kernel_launch(void* const* d_in, const int* in_sizes, int n_in,
                              void* d_out, int out_size) {
    const float* x  = (const float*)d_in[0];
    const void*  ei = d_in[1];
    const float* ew = (const float*)d_in[2];
    const float* W1 = (const float*)d_in[3];
    const float* b1 = (const float*)d_in[4];
    const float* W2 = (const float*)d_in[5];
    const float* b2 = (const float*)d_in[6];
    const float* W3 = (const float*)d_in[7];
    const float* b3 = (const float*)d_in[8];
    float* out = (float*)d_out;

    const int N = in_sizes[0] / IN_DIM;  // 100000
    const int E = in_sizes[1] / 2;       // 3200000
    (void)n_in; (void)out_size;

    float *h1, *h2, *h3;
    cudaGetSymbolAddress((void**)&h1, g_h1);
    cudaGetSymbolAddress((void**)&h2, g_h2);
    cudaGetSymbolAddress((void**)&h3, g_h3);

    const int nb_scan = (N + 1023) / 1024;

    // --- preprocessing: decode edges, degree, d^{-1/2}, CSR build -----------
    detect_kernel<<<1, 256>>>((const unsigned int*)ei, (long long)E * 2);
    zero_nd<<<cdiv(N, 256), 256>>>(N);
    convert_deg<<<cdiv(E, 256), 256>>>(ei, ew, E);
    dinv_kernel<<<cdiv(N, 256), 256>>>(N);
    scan_block<<<nb_scan, 1024>>>(N);
    scan_sums<<<1, 32>>>(nb_scan);
    add_offsets<<<cdiv(N, 256), 256>>>(N);
    scatter_csr<<<cdiv(E, 256), 256>>>(ew, E);

    // --- layer 1: h2 = relu(Anorm @ (x@W1^T) + b1) --------------------------
    gemm64<IN_DIM><<<cdiv(N, 64), 256>>>(x, W1, h1, N);
    spmm_gather64<1><<<cdiv((long long)N * 32, 256), 256>>>(h1, b1, h2, N, E);

    // --- layer 2 ------------------------------------------------------------
    gemm64<HID><<<cdiv(N, 64), 256>>>(h2, W2, h1, N);
    spmm_gather64<1><<<cdiv((long long)N * 32, 256), 256>>>(h1, b2, h2, N, E);

    // --- layer 3: out = Anorm @ (h2@W3^T) + b3 (no relu) --------------------
    gemm_k64_n10<<<cdiv(N, 128), 128>>>(h2, W3, h3, N);
    spmm_gather10<<<cdiv((long long)N * 32, 256), 256>>>(h3, b3, out, N, E);
}